// round 1
// baseline (speedup 1.0000x reference)
#include <cuda_runtime.h>

// SimpleNetworkAD: 480 independent 1->20->20->20->1 tanh MLPs, B=16384.
// Strategy: one node g per block (weights in SMEM, broadcast reads),
// 2 batch points per thread packed into f32x2 registers, all matmul FMAs
// issued as fma.rn.f32x2 (FFMA2) to double fp32 FMA throughput.

#define GNODE 480
#define HDIM  20
#define TPB   256

typedef unsigned long long u64;

__device__ __forceinline__ u64 f2_pack(float lo, float hi) {
    u64 r; asm("mov.b64 %0, {%1, %2};" : "=l"(r) : "f"(lo), "f"(hi)); return r;
}
__device__ __forceinline__ u64 f2_bcast(float v) {
    u64 r; asm("mov.b64 %0, {%1, %1};" : "=l"(r) : "f"(v)); return r;
}
__device__ __forceinline__ void f2_unpack(u64 v, float& lo, float& hi) {
    asm("mov.b64 {%0, %1}, %2;" : "=f"(lo), "=f"(hi) : "l"(v));
}
__device__ __forceinline__ u64 f2_fma(u64 a, u64 b, u64 c) {
    u64 d; asm("fma.rn.f32x2 %0, %1, %2, %3;" : "=l"(d) : "l"(a), "l"(b), "l"(c)); return d;
}
__device__ __forceinline__ u64 f2_mul(u64 a, u64 b) {
    u64 d; asm("mul.rn.f32x2 %0, %1, %2;" : "=l"(d) : "l"(a), "l"(b)); return d;
}
__device__ __forceinline__ float ex2a(float x) {
    float r; asm("ex2.approx.f32 %0, %1;" : "=f"(r) : "f"(x)); return r;
}
__device__ __forceinline__ float rcpa(float x) {
    float r; asm("rcp.approx.f32 %0, %1;" : "=f"(r) : "f"(x)); return r;
}

// tanh(x) = 1 - 2/(1 + e^{2x})  (accurate to ~1e-6; saturates correctly at +-1)
__device__ __forceinline__ u64 f2_tanh(u64 x) {
    u64 t = f2_mul(x, f2_bcast(2.8853900817779268f)); // 2*log2(e)
    float t0, t1; f2_unpack(t, t0, t1);
    float e0 = ex2a(t0), e1 = ex2a(t1);
    float r0 = rcpa(e0 + 1.0f);
    float r1 = rcpa(e1 + 1.0f);
    return f2_fma(f2_pack(r0, r1), f2_bcast(-2.0f), f2_bcast(1.0f));
}

__global__ void __launch_bounds__(TPB)
simple_network_ad_kernel(const float* __restrict__ x,
                         const float* __restrict__ W1, const float* __restrict__ B1,
                         const float* __restrict__ W2, const float* __restrict__ B2,
                         const float* __restrict__ W3, const float* __restrict__ B3,
                         const float* __restrict__ W4, const float* __restrict__ B4,
                         float* __restrict__ out, int n_b)
{
    __shared__ float sW1[HDIM], sB1[HDIM];
    __shared__ float sW2[HDIM * HDIM], sB2[HDIM];
    __shared__ float sW3[HDIM * HDIM], sB3[HDIM];
    __shared__ float sW4[HDIM];
    __shared__ float sB4;

    const int g   = blockIdx.y;
    const int tid = threadIdx.x;

    if (tid < HDIM) {
        sW1[tid] = W1[g * HDIM + tid];
        sB1[tid] = B1[g * HDIM + tid];
        sB2[tid] = B2[g * HDIM + tid];
        sB3[tid] = B3[g * HDIM + tid];
        sW4[tid] = W4[g * HDIM + tid];
    }
    if (tid == 0) sB4 = B4[g];
    for (int i = tid; i < HDIM * HDIM; i += TPB) {
        sW2[i] = W2[g * HDIM * HDIM + i];
        sW3[i] = W3[g * HDIM * HDIM + i];
    }
    __syncthreads();

    const int b0 = blockIdx.x * (TPB * 2) + tid;
    const int b1 = b0 + TPB;
    if (b0 >= n_b) return;

    float x0 = x[(size_t)b0 * GNODE + g];
    float x1 = (b1 < n_b) ? x[(size_t)b1 * GNODE + g] : 0.0f;
    u64 xin = f2_pack(x0, x1);

    u64 h[HDIM], acc[HDIM];

    // Layer 1: h = tanh(x * W1 + b1)
    #pragma unroll
    for (int i = 0; i < HDIM; i++)
        h[i] = f2_tanh(f2_fma(xin, f2_bcast(sW1[i]), f2_bcast(sB1[i])));

    // Layer 2: h = tanh(h @ W2 + b2)   h_next[l] = sum_k h[k] * W2[k][l]
    #pragma unroll
    for (int l = 0; l < HDIM; l++) acc[l] = f2_bcast(sB2[l]);
    #pragma unroll
    for (int k = 0; k < HDIM; k++) {
        u64 hk = h[k];
        #pragma unroll
        for (int l = 0; l < HDIM; l++)
            acc[l] = f2_fma(hk, f2_bcast(sW2[k * HDIM + l]), acc[l]);
    }
    #pragma unroll
    for (int l = 0; l < HDIM; l++) h[l] = f2_tanh(acc[l]);

    // Layer 3: h = tanh(h @ W3 + b3)
    #pragma unroll
    for (int l = 0; l < HDIM; l++) acc[l] = f2_bcast(sB3[l]);
    #pragma unroll
    for (int k = 0; k < HDIM; k++) {
        u64 hk = h[k];
        #pragma unroll
        for (int l = 0; l < HDIM; l++)
            acc[l] = f2_fma(hk, f2_bcast(sW3[k * HDIM + l]), acc[l]);
    }
    #pragma unroll
    for (int l = 0; l < HDIM; l++) h[l] = f2_tanh(acc[l]);

    // Layer 4: out = h . W4 + b4
    u64 o = f2_bcast(sB4);
    #pragma unroll
    for (int k = 0; k < HDIM; k++)
        o = f2_fma(h[k], f2_bcast(sW4[k]), o);

    float o0, o1;
    f2_unpack(o, o0, o1);
    out[(size_t)b0 * GNODE + g] = o0;
    if (b1 < n_b) out[(size_t)b1 * GNODE + g] = o1;
}

extern "C" void kernel_launch(void* const* d_in, const int* in_sizes, int n_in,
                              void* d_out, int out_size)
{
    const float* x  = (const float*)d_in[0];
    const float* W1 = (const float*)d_in[1];
    const float* B1 = (const float*)d_in[2];
    const float* W2 = (const float*)d_in[3];
    const float* B2 = (const float*)d_in[4];
    const float* W3 = (const float*)d_in[5];
    const float* B3 = (const float*)d_in[6];
    const float* W4 = (const float*)d_in[7];
    const float* B4 = (const float*)d_in[8];
    float* out = (float*)d_out;

    int n_b = in_sizes[0] / GNODE;                 // 16384
    int chunks = (n_b + TPB * 2 - 1) / (TPB * 2);  // 32
    dim3 grid(chunks, GNODE);
    simple_network_ad_kernel<<<grid, TPB>>>(x, W1, B1, W2, B2, W3, B3, W4, B4, out, n_b);
}